// round 1
// baseline (speedup 1.0000x reference)
#include <cuda_runtime.h>
#include <math.h>

#define DTF 0.1f
#define DIM_D 64
#define DIM_H 128
#define TILE_M 64
#define NTHREADS 256

__device__ unsigned g_maxabs;
__device__ int g_steps;

__global__ void k_init_red() { g_maxabs = 0u; }

__global__ void k_reduce_max(const float* __restrict__ td, int n) {
    unsigned m = 0u;
    for (int i = blockIdx.x * blockDim.x + threadIdx.x; i < n; i += gridDim.x * blockDim.x)
        m = max(m, __float_as_uint(fabsf(td[i])));
    #pragma unroll
    for (int o = 16; o > 0; o >>= 1)
        m = max(m, __shfl_xor_sync(0xFFFFFFFFu, m, o));
    if ((threadIdx.x & 31) == 0) atomicMax(&g_maxabs, m);
}

__global__ void k_finalize_steps() {
    // match numpy: steps = int(ceil(float64(max) / 0.1))
    double mx = (double)__uint_as_float(g_maxabs);
    g_steps = (int)ceil(mx / 0.1);
}

struct SmemLayout {
    float Wz[DIM_D][DIM_H];   // W1[:-1], [k][n]
    float W2[DIM_H][DIM_H];   // [k][n]
    float W3[DIM_H][DIM_D];   // [k][n]
    float b1[DIM_H];
    float Wt[DIM_H];          // W1[-1]
    float b2[DIM_H];
    float b3[DIM_D];
    float Z[TILE_M][DIM_D];
    float H1[TILE_M][DIM_H];
    float H2[TILE_M][DIM_H];
    float adt[TILE_M];
};

extern __shared__ float smem_raw[];

__global__ void __launch_bounds__(NTHREADS, 1)
ode_kernel(const float* __restrict__ z, const float* __restrict__ td,
           const float* __restrict__ W1, const float* __restrict__ b1,
           const float* __restrict__ W2, const float* __restrict__ b2,
           const float* __restrict__ W3, const float* __restrict__ b3,
           float* __restrict__ out)
{
    SmemLayout& S = *reinterpret_cast<SmemLayout*>(smem_raw);
    const int tid = threadIdx.x;
    const int row0 = blockIdx.x * TILE_M;

    // ---- cooperative weight load (float4, coalesced; all weights fit in L2 so
    // repeated per-CTA loads are L2 hits) ----
    for (int i = tid; i < DIM_D * DIM_H / 4; i += NTHREADS)
        ((float4*)S.Wz)[i] = ((const float4*)W1)[i];
    for (int i = tid; i < DIM_H / 4; i += NTHREADS)
        ((float4*)S.Wt)[i] = ((const float4*)(W1 + DIM_D * DIM_H))[i];
    for (int i = tid; i < DIM_H * DIM_H / 4; i += NTHREADS)
        ((float4*)S.W2)[i] = ((const float4*)W2)[i];
    for (int i = tid; i < DIM_H * DIM_D / 4; i += NTHREADS)
        ((float4*)S.W3)[i] = ((const float4*)W3)[i];
    if (tid < DIM_H / 4) {
        ((float4*)S.b1)[tid] = ((const float4*)b1)[tid];
        ((float4*)S.b2)[tid] = ((const float4*)b2)[tid];
    }
    if (tid >= 64 && tid < 64 + DIM_D / 4)
        ((float4*)S.b3)[tid - 64] = ((const float4*)b3)[tid - 64];

    const int steps = g_steps;

    // ---- load Z tile + per-row dt ----
    for (int i = tid; i < TILE_M * DIM_D / 4; i += NTHREADS)
        ((float4*)S.Z)[i] = ((const float4*)(z + (size_t)row0 * DIM_D))[i];
    if (tid < TILE_M)
        S.adt[tid] = (steps > 0) ? td[row0 + tid] / (float)steps : 0.0f;
    __syncthreads();

    // L1/L2 mapping: 32 threads along N (4 cols each), 8 along M (8 rows each)
    const int tx = tid & 31, ty = tid >> 5;
    // L3 mapping: 16 threads along N (4 cols), 16 along M (4 rows)
    const int ux = tid & 15, vy = tid >> 4;

    for (int s = 0; s < steps; ++s) {
        const float t = (float)s * DTF;

        // ================= Layer 1: H1 = tanh(Z @ Wz + t*Wt + b1) =================
        {
            const int c0 = tx * 4, r0 = ty * 8;
            float acc[8][4];
            float4 bb = *(const float4*)&S.b1[c0];
            float4 wt = *(const float4*)&S.Wt[c0];
            const float i0 = fmaf(t, wt.x, bb.x), i1 = fmaf(t, wt.y, bb.y);
            const float i2 = fmaf(t, wt.z, bb.z), i3 = fmaf(t, wt.w, bb.w);
            #pragma unroll
            for (int i = 0; i < 8; i++) { acc[i][0]=i0; acc[i][1]=i1; acc[i][2]=i2; acc[i][3]=i3; }

            #pragma unroll
            for (int k = 0; k < DIM_D; k += 4) {
                float4 a[8];
                #pragma unroll
                for (int i = 0; i < 8; i++) a[i] = *(const float4*)&S.Z[r0 + i][k];
                #pragma unroll
                for (int kk = 0; kk < 4; kk++) {
                    float4 w = *(const float4*)&S.Wz[k + kk][c0];
                    #pragma unroll
                    for (int i = 0; i < 8; i++) {
                        const float av = ((const float*)&a[i])[kk];
                        acc[i][0] = fmaf(av, w.x, acc[i][0]);
                        acc[i][1] = fmaf(av, w.y, acc[i][1]);
                        acc[i][2] = fmaf(av, w.z, acc[i][2]);
                        acc[i][3] = fmaf(av, w.w, acc[i][3]);
                    }
                }
            }
            #pragma unroll
            for (int i = 0; i < 8; i++) {
                float4 hv;
                hv.x = tanhf(acc[i][0]); hv.y = tanhf(acc[i][1]);
                hv.z = tanhf(acc[i][2]); hv.w = tanhf(acc[i][3]);
                *(float4*)&S.H1[r0 + i][c0] = hv;
            }
        }
        __syncthreads();

        // ================= Layer 2: H2 = tanh(H1 @ W2 + b2) =================
        {
            const int c0 = tx * 4, r0 = ty * 8;
            float acc[8][4];
            float4 bb = *(const float4*)&S.b2[c0];
            #pragma unroll
            for (int i = 0; i < 8; i++) { acc[i][0]=bb.x; acc[i][1]=bb.y; acc[i][2]=bb.z; acc[i][3]=bb.w; }

            #pragma unroll 8
            for (int k = 0; k < DIM_H; k += 4) {
                float4 a[8];
                #pragma unroll
                for (int i = 0; i < 8; i++) a[i] = *(const float4*)&S.H1[r0 + i][k];
                #pragma unroll
                for (int kk = 0; kk < 4; kk++) {
                    float4 w = *(const float4*)&S.W2[k + kk][c0];
                    #pragma unroll
                    for (int i = 0; i < 8; i++) {
                        const float av = ((const float*)&a[i])[kk];
                        acc[i][0] = fmaf(av, w.x, acc[i][0]);
                        acc[i][1] = fmaf(av, w.y, acc[i][1]);
                        acc[i][2] = fmaf(av, w.z, acc[i][2]);
                        acc[i][3] = fmaf(av, w.w, acc[i][3]);
                    }
                }
            }
            #pragma unroll
            for (int i = 0; i < 8; i++) {
                float4 hv;
                hv.x = tanhf(acc[i][0]); hv.y = tanhf(acc[i][1]);
                hv.z = tanhf(acc[i][2]); hv.w = tanhf(acc[i][3]);
                *(float4*)&S.H2[r0 + i][c0] = hv;
            }
        }
        __syncthreads();

        // ============ Layer 3: dz = H2 @ W3 + b3 ; Z += dz * adt ============
        {
            const int c0 = ux * 4, r0 = vy * 4;
            float acc[4][4];
            float4 bb = *(const float4*)&S.b3[c0];
            #pragma unroll
            for (int i = 0; i < 4; i++) { acc[i][0]=bb.x; acc[i][1]=bb.y; acc[i][2]=bb.z; acc[i][3]=bb.w; }

            #pragma unroll 8
            for (int k = 0; k < DIM_H; k += 4) {
                float4 a[4];
                #pragma unroll
                for (int i = 0; i < 4; i++) a[i] = *(const float4*)&S.H2[r0 + i][k];
                #pragma unroll
                for (int kk = 0; kk < 4; kk++) {
                    float4 w = *(const float4*)&S.W3[k + kk][c0];
                    #pragma unroll
                    for (int i = 0; i < 4; i++) {
                        const float av = ((const float*)&a[i])[kk];
                        acc[i][0] = fmaf(av, w.x, acc[i][0]);
                        acc[i][1] = fmaf(av, w.y, acc[i][1]);
                        acc[i][2] = fmaf(av, w.z, acc[i][2]);
                        acc[i][3] = fmaf(av, w.w, acc[i][3]);
                    }
                }
            }
            #pragma unroll
            for (int i = 0; i < 4; i++) {
                const float ad = S.adt[r0 + i];
                float4 zv = *(const float4*)&S.Z[r0 + i][c0];
                zv.x = fmaf(acc[i][0], ad, zv.x);
                zv.y = fmaf(acc[i][1], ad, zv.y);
                zv.z = fmaf(acc[i][2], ad, zv.z);
                zv.w = fmaf(acc[i][3], ad, zv.w);
                *(float4*)&S.Z[r0 + i][c0] = zv;
            }
        }
        __syncthreads();
    }

    // ---- write back ----
    for (int i = tid; i < TILE_M * DIM_D / 4; i += NTHREADS)
        ((float4*)(out + (size_t)row0 * DIM_D))[i] = ((const float4*)S.Z)[i];
}

extern "C" void kernel_launch(void* const* d_in, const int* in_sizes, int n_in,
                              void* d_out, int out_size)
{
    const float* z  = (const float*)d_in[0];
    const float* td = (const float*)d_in[1];
    const float* W1 = (const float*)d_in[2];
    const float* b1 = (const float*)d_in[3];
    const float* W2 = (const float*)d_in[4];
    const float* b2 = (const float*)d_in[5];
    const float* W3 = (const float*)d_in[6];
    const float* b3 = (const float*)d_in[7];
    float* out = (float*)d_out;

    const int B = in_sizes[1];          // time_delta element count == batch
    const int smem_bytes = (int)sizeof(SmemLayout);

    static bool attr_set = false;
    if (!attr_set) {
        cudaFuncSetAttribute(ode_kernel,
                             cudaFuncAttributeMaxDynamicSharedMemorySize,
                             smem_bytes);
        attr_set = true;
    }

    k_init_red<<<1, 1>>>();
    k_reduce_max<<<64, 256>>>(td, B);
    k_finalize_steps<<<1, 1>>>();

    const int grid = B / TILE_M;  // 65536/64 = 1024
    ode_kernel<<<grid, NTHREADS, smem_bytes>>>(z, td, W1, b1, W2, b2, W3, b3, out);
}

// round 3
// speedup vs baseline: 1.1804x; 1.1804x over previous
#include <cuda_runtime.h>
#include <mma.h>
#include <cstdint>
#include <math.h>

using namespace nvcuda;

#define DTF 0.1f
#define DIM_D 64
#define DIM_H 128
#define TILE_M 128
#define NT 256

#define LDH 132   // padded stride for 128-col buffers (floats)
#define LDN 68    // padded stride for 64-col buffers (floats)

// ---- SMEM float offsets ----
#define OFF_WZ   0                         // 64 x LDH
#define OFF_W2   (OFF_WZ + 64 * LDH)       // 128 x LDH
#define OFF_W3   (OFF_W2 + 128 * LDH)      // 128 x LDN
#define OFF_ACT  (OFF_W3 + 128 * LDN)      // 128 x LDH (time-shared: Zr/dz use stride LDN region)
#define OFF_CMB  (OFF_ACT + 128 * LDH)     // 16 x LDH  (t*Wt + b1, replicated rows)
#define OFF_B2T  (OFF_CMB + 16 * LDH)      // 16 x LDH
#define OFF_B3T  (OFF_B2T + 16 * LDH)      // 16 x LDN
#define OFF_WT   (OFF_B3T + 16 * LDN)      // 128
#define OFF_B1   (OFF_WT + 128)            // 128
#define SMEM_FLOATS (OFF_B1 + 128)
#define SMEM_BYTES  (SMEM_FLOATS * 4)      // 226048 B

__device__ __forceinline__ float tf32r(float x) {
    float o; asm("cvt.rna.tf32.f32 %0, %1;" : "=f"(o) : "f"(x)); return o;
}
// tanh(x) = 1 - 2/(exp2(2x*log2e)+1)  (2 MUFU, ~1e-6 abs err)
__device__ __forceinline__ float ftanh(float x) {
    float a = fminf(x * 2.8853900817779268f, 80.0f);
    float e; asm("ex2.approx.f32 %0, %1;" : "=f"(e) : "f"(a));
    float r; asm("rcp.approx.f32 %0, %1;" : "=f"(r) : "f"(e + 1.0f));
    return fmaf(-2.0f, r, 1.0f);
}

// ---------------- steps computation ----------------
__device__ unsigned g_maxabs;
__device__ int g_steps;
__global__ void k_init_red() { g_maxabs = 0u; }
__global__ void k_reduce_max(const float* __restrict__ td, int n) {
    unsigned m = 0u;
    for (int i = blockIdx.x * blockDim.x + threadIdx.x; i < n; i += gridDim.x * blockDim.x)
        m = max(m, __float_as_uint(fabsf(td[i])));
    #pragma unroll
    for (int o = 16; o > 0; o >>= 1) m = max(m, __shfl_xor_sync(0xFFFFFFFFu, m, o));
    if ((threadIdx.x & 31) == 0) atomicMax(&g_maxabs, m);
}
__global__ void k_finalize_steps() {
    double mx = (double)__uint_as_float(g_maxabs);
    g_steps = (int)ceil(mx / 0.1);
}

extern __shared__ float sm[];

typedef wmma::fragment<wmma::matrix_a, 16, 16, 8, wmma::precision::tf32, wmma::row_major> FragA;
typedef wmma::fragment<wmma::matrix_b, 16, 16, 8, wmma::precision::tf32, wmma::row_major> FragB;
typedef wmma::fragment<wmma::accumulator, 16, 16, 8, float> FragC;

__global__ void __launch_bounds__(NT, 1)
ode_mma_kernel(const float* __restrict__ z, const float* __restrict__ td,
               const float* __restrict__ W1, const float* __restrict__ b1,
               const float* __restrict__ W2, const float* __restrict__ b2,
               const float* __restrict__ W3, const float* __restrict__ b3,
               float* __restrict__ out)
{
    const int tid  = threadIdx.x;
    const int warp = tid >> 5;
    const int rg   = warp >> 1;          // row group 0..3 -> rows rg*32 .. +32
    const int ch   = warp & 1;           // col half  0..1
    const int row0 = blockIdx.x * TILE_M;

    float* Wzs = sm + OFF_WZ;
    float* W2s = sm + OFF_W2;
    float* W3s = sm + OFF_W3;
    float* ACT = sm + OFF_ACT;           // H buffer (stride LDH); front also Zr/dz (stride LDN)
    float* CMB = sm + OFF_CMB;
    float* B2T = sm + OFF_B2T;
    float* B3T = sm + OFF_B3T;
    float* WTv = sm + OFF_WT;
    float* B1v = sm + OFF_B1;

    // ---- stage weights (rounded to tf32) ----
    for (int i = tid; i < DIM_D * DIM_H; i += NT) {
        int k = i >> 7, n = i & 127;
        Wzs[k * LDH + n] = tf32r(W1[i]);
    }
    for (int i = tid; i < DIM_H * DIM_H; i += NT) {
        int k = i >> 7, n = i & 127;
        W2s[k * LDH + n] = tf32r(W2[i]);
    }
    for (int i = tid; i < DIM_H * DIM_D; i += NT) {
        int k = i >> 6, n = i & 63;
        W3s[k * LDN + n] = tf32r(W3[i]);
    }
    if (tid < DIM_H) {
        WTv[tid] = W1[DIM_D * DIM_H + tid];
        B1v[tid] = b1[tid];
        float v2 = b2[tid];
        #pragma unroll
        for (int r = 0; r < 16; r++) B2T[r * LDH + tid] = v2;
        if (tid < DIM_D) {
            float v3 = b3[tid];
            #pragma unroll
            for (int r = 0; r < 16; r++) B3T[r * LDN + tid] = v3;
        }
    }

    // ---- z master in registers; write tf32 copy (Zr) into ACT front (stride LDN) ----
    const int myrow = tid >> 1;
    const int c0    = (tid & 1) * 32;
    const int steps = g_steps;
    const float adt = (steps > 0) ? td[row0 + myrow] / (float)steps : 0.0f;

    float zreg[32];
    {
        const float4* zp = (const float4*)(z + (size_t)(row0 + myrow) * DIM_D + c0);
        #pragma unroll
        for (int j = 0; j < 8; j++) {
            float4 v = zp[j];
            zreg[j*4+0] = v.x; zreg[j*4+1] = v.y; zreg[j*4+2] = v.z; zreg[j*4+3] = v.w;
        }
        #pragma unroll
        for (int j = 0; j < 32; j++) ACT[myrow * LDN + c0 + j] = tf32r(zreg[j]);
    }
    __syncthreads();

    const int colA = ch * 64;   // 64-wide col range for L1/L2 output
    const int colB = ch * 32;   // 32-wide col range for L3 output
    const int rbase = rg * 32;

    for (int s = 0; s < steps; ++s) {
        // combo = t*Wt + b1 (replicated 16 rows)
        if (tid < DIM_H) {
            float cv = fmaf((float)s * DTF, WTv[tid], B1v[tid]);
            #pragma unroll
            for (int r = 0; r < 16; r++) CMB[r * LDH + tid] = cv;
        }
        __syncthreads();

        // ===== L1: D1 = Zr @ Wz + combo ; H1 = tanh -> ACT (stride LDH) =====
        {
            FragC acc[2][4];
            #pragma unroll
            for (int rt = 0; rt < 2; rt++)
                #pragma unroll
                for (int nt = 0; nt < 4; nt++)
                    wmma::load_matrix_sync(acc[rt][nt], CMB + colA + nt * 16, LDH, wmma::mem_row_major);
            #pragma unroll
            for (int k = 0; k < 8; k++) {
                FragA a0, a1;
                wmma::load_matrix_sync(a0, ACT + (rbase +  0) * LDN + k * 8, LDN);
                wmma::load_matrix_sync(a1, ACT + (rbase + 16) * LDN + k * 8, LDN);
                #pragma unroll
                for (int nt = 0; nt < 4; nt++) {
                    FragB b;
                    wmma::load_matrix_sync(b, Wzs + (k * 8) * LDH + colA + nt * 16, LDH);
                    wmma::mma_sync(acc[0][nt], a0, b, acc[0][nt]);
                    wmma::mma_sync(acc[1][nt], a1, b, acc[1][nt]);
                }
            }
            #pragma unroll
            for (int rt = 0; rt < 2; rt++)
                #pragma unroll
                for (int nt = 0; nt < 4; nt++)
                    #pragma unroll
                    for (int e = 0; e < acc[rt][nt].num_elements; e++)
                        acc[rt][nt].x[e] = tf32r(ftanh(acc[rt][nt].x[e]));
            __syncthreads();   // all Zr reads done before overwrite
            #pragma unroll
            for (int rt = 0; rt < 2; rt++)
                #pragma unroll
                for (int nt = 0; nt < 4; nt++)
                    wmma::store_matrix_sync(ACT + (rbase + rt * 16) * LDH + colA + nt * 16,
                                            acc[rt][nt], LDH, wmma::mem_row_major);
            __syncthreads();
        }

        // ===== L2: H2 = tanh(H1 @ W2 + b2) -> ACT in place =====
        {
            FragC acc[2][4];
            #pragma unroll
            for (int rt = 0; rt < 2; rt++)
                #pragma unroll
                for (int nt = 0; nt < 4; nt++)
                    wmma::load_matrix_sync(acc[rt][nt], B2T + colA + nt * 16, LDH, wmma::mem_row_major);
            #pragma unroll
            for (int k = 0; k < 16; k++) {
                FragA a0, a1;
                wmma::load_matrix_sync(a0, ACT + (rbase +  0) * LDH + k * 8, LDH);
                wmma::load_matrix_sync(a1, ACT + (rbase + 16) * LDH + k * 8, LDH);
                #pragma unroll
                for (int nt = 0; nt < 4; nt++) {
                    FragB b;
                    wmma::load_matrix_sync(b, W2s + (k * 8) * LDH + colA + nt * 16, LDH);
                    wmma::mma_sync(acc[0][nt], a0, b, acc[0][nt]);
                    wmma::mma_sync(acc[1][nt], a1, b, acc[1][nt]);
                }
            }
            #pragma unroll
            for (int rt = 0; rt < 2; rt++)
                #pragma unroll
                for (int nt = 0; nt < 4; nt++)
                    #pragma unroll
                    for (int e = 0; e < acc[rt][nt].num_elements; e++)
                        acc[rt][nt].x[e] = tf32r(ftanh(acc[rt][nt].x[e]));
            __syncthreads();
            #pragma unroll
            for (int rt = 0; rt < 2; rt++)
                #pragma unroll
                for (int nt = 0; nt < 4; nt++)
                    wmma::store_matrix_sync(ACT + (rbase + rt * 16) * LDH + colA + nt * 16,
                                            acc[rt][nt], LDH, wmma::mem_row_major);
            __syncthreads();
        }

        // ===== L3: dz = H2 @ W3 + b3 -> ACT front (stride LDN) =====
        {
            FragC acc[2][2];
            #pragma unroll
            for (int rt = 0; rt < 2; rt++)
                #pragma unroll
                for (int nt = 0; nt < 2; nt++)
                    wmma::load_matrix_sync(acc[rt][nt], B3T + colB + nt * 16, LDN, wmma::mem_row_major);
            #pragma unroll
            for (int k = 0; k < 16; k++) {
                FragA a0, a1;
                wmma::load_matrix_sync(a0, ACT + (rbase +  0) * LDH + k * 8, LDH);
                wmma::load_matrix_sync(a1, ACT + (rbase + 16) * LDH + k * 8, LDH);
                #pragma unroll
                for (int nt = 0; nt < 2; nt++) {
                    FragB b;
                    wmma::load_matrix_sync(b, W3s + (k * 8) * LDN + colB + nt * 16, LDN);
                    wmma::mma_sync(acc[0][nt], a0, b, acc[0][nt]);
                    wmma::mma_sync(acc[1][nt], a1, b, acc[1][nt]);
                }
            }
            __syncthreads();   // all H2 reads done before dz overwrites front
            #pragma unroll
            for (int rt = 0; rt < 2; rt++)
                #pragma unroll
                for (int nt = 0; nt < 2; nt++)
                    wmma::store_matrix_sync(ACT + (rbase + rt * 16) * LDN + colB + nt * 16,
                                            acc[rt][nt], LDN, wmma::mem_row_major);
            __syncthreads();
        }

        // ===== z update: z += dz*adt (fp32 master in regs); refresh Zr =====
        #pragma unroll
        for (int j = 0; j < 32; j++) {
            float d = ACT[myrow * LDN + c0 + j];
            zreg[j] = fmaf(d, adt, zreg[j]);
            ACT[myrow * LDN + c0 + j] = tf32r(zreg[j]);
        }
        __syncthreads();
    }

    // ---- write out fp32 master ----
    {
        float4* op = (float4*)(out + (size_t)(row0 + myrow) * DIM_D + c0);
        #pragma unroll
        for (int j = 0; j < 8; j++) {
            float4 v;
            v.x = zreg[j*4+0]; v.y = zreg[j*4+1]; v.z = zreg[j*4+2]; v.w = zreg[j*4+3];
            op[j] = v;
        }
    }
}

extern "C" void kernel_launch(void* const* d_in, const int* in_sizes, int n_in,
                              void* d_out, int out_size)
{
    const float* z  = (const float*)d_in[0];
    const float* td = (const float*)d_in[1];
    const float* W1 = (const float*)d_in[2];
    const float* b1 = (const float*)d_in[3];
    const float* W2 = (const float*)d_in[4];
    const float* b2 = (const float*)d_in[5];
    const float* W3 = (const float*)d_in[6];
    const float* b3 = (const float*)d_in[7];
    float* out = (float*)d_out;

    const int B = in_sizes[1];

    cudaFuncSetAttribute(ode_mma_kernel,
                         cudaFuncAttributeMaxDynamicSharedMemorySize, SMEM_BYTES);

    k_init_red<<<1, 1>>>();
    k_reduce_max<<<64, 256>>>(td, B);
    k_finalize_steps<<<1, 1>>>();

    const int grid = B / TILE_M;   // 512
    ode_mma_kernel<<<grid, NT, SMEM_BYTES>>>(z, td, W1, b1, W2, b2, W3, b3, out);
}